// round 5
// baseline (speedup 1.0000x reference)
#include <cuda_runtime.h>
#include <math.h>
#include <stdint.h>

#define SEQ 4096
#define HID 1024
#define NH  16
#define HD  64

// Scratch (allocation-free rule: __device__ globals)
__device__ float g_Q[SEQ * HID];
__device__ float g_K[SEQ * HID];
__device__ float g_V[SEQ * HID];
__device__ float g_C[SEQ * HID];
__device__ float g_Xr[SEQ * HID];
__device__ float g_Wqr[HID * HID];
__device__ float g_Wkr[HID * HID];
__device__ float g_Wvr[HID * HID];
__device__ float g_Wor[HID * HID];

// ---------------------------------------------------------------------------
// helpers
// ---------------------------------------------------------------------------
__device__ __forceinline__ float tf32r(float x) {
    uint32_t u;
    asm("cvt.rna.tf32.f32 %0, %1;" : "=r"(u) : "f"(x));
    return __uint_as_float(u);
}

__device__ __forceinline__ void mma_tf32(float (&d)[4], const uint32_t (&a)[4],
                                         uint32_t b0, uint32_t b1) {
    asm volatile(
        "mma.sync.aligned.m16n8k8.row.col.f32.tf32.tf32.f32 "
        "{%0,%1,%2,%3}, {%4,%5,%6,%7}, {%8,%9}, {%0,%1,%2,%3};\n"
        : "+f"(d[0]), "+f"(d[1]), "+f"(d[2]), "+f"(d[3])
        : "r"(a[0]), "r"(a[1]), "r"(a[2]), "r"(a[3]), "r"(b0), "r"(b1));
}

__device__ __forceinline__ uint32_t sptr(const void* p) {
    return (uint32_t)__cvta_generic_to_shared(p);
}
#define CPA16(dst, src) \
    asm volatile("cp.async.cg.shared.global [%0], [%1], 16;" :: "r"(dst), "l"(src))
#define CPC() asm volatile("cp.async.commit_group;")
#define CPW(N) asm volatile("cp.async.wait_group %0;" :: "n"(N))

// ---------------------------------------------------------------------------
// tf32 pre-rounding (vectorized)
// ---------------------------------------------------------------------------
__global__ void round_tf32_kernel(const float4* __restrict__ src,
                                  float4* __restrict__ dst, int n4) {
    int i = blockIdx.x * blockDim.x + threadIdx.x;
    if (i < n4) {
        float4 v = src[i];
        dst[i] = make_float4(tf32r(v.x), tf32r(v.y), tf32r(v.z), tf32r(v.w));
    }
}

// ---------------------------------------------------------------------------
// tf32 GEMM: C[M,N] = A[M,K] @ B[N,K]^T. Operands pre-rounded in gmem.
// 2-stage cp.async pipeline, BM=BN=128, BK=32, 256 threads, 8 warps 4x2.
// Smem pitch 36 floats (144B, 16B-aligned rows) -> conflict-free LDS, valid cp dst.
// ROPE: apply rotary to output pairs (t, t+4) in registers. !BIAS => round output.
// ---------------------------------------------------------------------------
template <bool BIAS, bool ROPE>
__global__ __launch_bounds__(256)
void gemm_tf32(const float* __restrict__ A, const float* __restrict__ B,
               const float* __restrict__ bias, const int* __restrict__ pos,
               float* __restrict__ C, int M, int N, int K) {
    extern __shared__ float smem[];
    float* Asb[2] = {smem, smem + 4608};
    float* Bsb[2] = {smem + 9216, smem + 13824};

    const int tid = threadIdx.x;
    const int lane = tid & 31;
    const int w = tid >> 5;
    const int wm = w & 3;
    const int wn = w >> 2;
    const int rowBase = blockIdx.y * 128;
    const int colBase = blockIdx.x * 128;

    float acc[16][4];
#pragma unroll
    for (int i = 0; i < 16; i++)
#pragma unroll
        for (int j = 0; j < 4; j++) acc[i][j] = 0.f;

    const int ldrow = tid >> 1;            // 0..127
    const int ldcol = (tid & 1) * 16;      // float offset 0 or 16

    // stage loader: 4 x 16B per thread per matrix
    auto load_stage = [&](int k0, int buf) {
        const float* Ag = &A[(rowBase + ldrow) * K + k0 + ldcol];
        const float* Bg = &B[(colBase + ldrow) * K + k0 + ldcol];
        uint32_t da = sptr(&Asb[buf][ldrow * 36 + ldcol]);
        uint32_t db = sptr(&Bsb[buf][ldrow * 36 + ldcol]);
#pragma unroll
        for (int i = 0; i < 4; i++) {
            CPA16(da + i * 16, Ag + i * 4);
            CPA16(db + i * 16, Bg + i * 4);
        }
    };

    load_stage(0, 0);
    CPC();

    const int NK = K / 32;
    for (int s = 0; s < NK; s++) {
        if (s + 1 < NK) { load_stage((s + 1) * 32, (s + 1) & 1); CPC(); CPW(1); }
        else            { CPW(0); }
        __syncthreads();

        const float* As = Asb[s & 1];
        const float* Bs = Bsb[s & 1];
#pragma unroll
        for (int kk = 0; kk < 32; kk += 8) {
            uint32_t a[2][4];
#pragma unroll
            for (int mt = 0; mt < 2; mt++) {
                int ar = wm * 32 + mt * 16 + (lane >> 2);
                int ac = kk + (lane & 3);
                a[mt][0] = __float_as_uint(As[ar * 36 + ac]);
                a[mt][1] = __float_as_uint(As[(ar + 8) * 36 + ac]);
                a[mt][2] = __float_as_uint(As[ar * 36 + ac + 4]);
                a[mt][3] = __float_as_uint(As[(ar + 8) * 36 + ac + 4]);
            }
#pragma unroll
            for (int t = 0; t < 8; t++) {
                int br = wn * 64 + t * 8 + (lane >> 2);
                int bc = kk + (lane & 3);
                uint32_t b0 = __float_as_uint(Bs[br * 36 + bc]);
                uint32_t b1 = __float_as_uint(Bs[br * 36 + bc + 4]);
                mma_tf32(acc[t], a[0], b0, b1);
                mma_tf32(acc[8 + t], a[1], b0, b1);
            }
        }
        __syncthreads();
    }

    if (ROPE) {
        // theta for the 8 head-dim columns this thread owns (j = t*8+2(lane&3)+b)
        float th[8];
#pragma unroll
        for (int t = 0; t < 4; t++)
#pragma unroll
            for (int b = 0; b < 2; b++) {
                int j = t * 8 + 2 * (lane & 3) + b;
                th[t * 2 + b] = expf(-(float)j * (9.210340371976184f / 32.0f));
            }
#pragma unroll
        for (int mt = 0; mt < 2; mt++) {
            int r0 = rowBase + wm * 32 + mt * 16 + (lane >> 2);
            float p0 = (float)pos[r0];
            float p1 = (float)pos[r0 + 8];
#pragma unroll
            for (int t = 0; t < 4; t++) {
#pragma unroll
                for (int jj = 0; jj < 4; jj++) {
                    float pv = (jj < 2) ? p0 : p1;
                    float sn, cs;
                    sincosf(pv * th[t * 2 + (jj & 1)], &sn, &cs);
                    float x1 = acc[mt * 8 + t][jj];
                    float x2 = acc[mt * 8 + t + 4][jj];
                    acc[mt * 8 + t][jj]     = x1 * cs - x2 * sn;
                    acc[mt * 8 + t + 4][jj] = x1 * sn + x2 * cs;
                }
            }
        }
    }

#pragma unroll
    for (int mt = 0; mt < 2; mt++) {
#pragma unroll
        for (int t = 0; t < 8; t++) {
            int r0 = rowBase + wm * 32 + mt * 16 + (lane >> 2);
            int c0 = colBase + wn * 64 + t * 8 + 2 * (lane & 3);
            float* d = acc[mt * 8 + t];
            float v0 = d[0], v1 = d[1], v2 = d[2], v3 = d[3];
            if (BIAS) {
                float bb0 = bias[c0], bb1 = bias[c0 + 1];
                v0 += bb0; v1 += bb1; v2 += bb0; v3 += bb1;
            } else {
                v0 = tf32r(v0); v1 = tf32r(v1); v2 = tf32r(v2); v3 = tf32r(v3);
            }
            *(float2*)&C[r0 * N + c0] = make_float2(v0, v1);
            *(float2*)&C[(r0 + 8) * N + c0] = make_float2(v2, v3);
        }
    }
}

// ---------------------------------------------------------------------------
// Causal flash attention, tf32 MMA, cp.async double-buffered K/V.
// BR=128, BC=64. 8 warps; warp w owns rows [16w,16w+16).
// Qs/Ks/Ps pitch 68 (272B rows, 16B aligned); Vs pitch 72 (288B).
// Inputs Q/K/V pre-rounded to tf32 in gmem. Output rounded for Wo GEMM.
// ---------------------------------------------------------------------------
__global__ __launch_bounds__(256)
void flash_attn(const float* __restrict__ Q, const float* __restrict__ K,
                const float* __restrict__ V, float* __restrict__ O) {
    extern __shared__ float sm[];
    float* Qs = sm;                               // 128 x 68
    float* Ksb[2] = {sm + 8704, sm + 13056};      // 2 x (64 x 68)
    float* Vsb[2] = {sm + 17408, sm + 22016};     // 2 x (64 x 72)
    float* Ps = sm + 26624;                       // 128 x 68
    float* mrow = sm + 35328;
    float* lrow = mrow + 128;
    float* arow = lrow + 128;

    const int tid = threadIdx.x;
    const int lane = tid & 31;
    const int w = tid >> 5;
    const int qb = gridDim.x - 1 - blockIdx.x;    // heavy blocks first
    const int h = blockIdx.y;
    const int qBase = qb * 128;
    const int hoff = h * HD;
    const float scale = 0.125f;

    auto load_kv = [&](int kb, int buf) {
        const int kBase = kb * 64;
        float* Ks = Ksb[buf];
        float* Vs = Vsb[buf];
        for (int i = tid; i < 2048; i += 256) {
            if (i < 1024) {
                int r = i >> 4, ch = (i & 15) * 4;
                CPA16(sptr(&Ks[r * 68 + ch]), &K[(kBase + r) * HID + hoff + ch]);
            } else {
                int i2 = i - 1024;
                int r = i2 >> 4, ch = (i2 & 15) * 4;
                CPA16(sptr(&Vs[r * 72 + ch]), &V[(kBase + r) * HID + hoff + ch]);
            }
        }
    };

    // stage Q + first K/V tile in group 0
    for (int i = tid; i < 2048; i += 256) {
        int r = i >> 4, ch = (i & 15) * 4;
        CPA16(sptr(&Qs[r * 68 + ch]), &Q[(qBase + r) * HID + hoff + ch]);
    }
    load_kv(0, 0);
    CPC();

    if (tid < 128) { mrow[tid] = -1e30f; lrow[tid] = 0.f; }

    float o[8][4];
#pragma unroll
    for (int t = 0; t < 8; t++)
#pragma unroll
        for (int j = 0; j < 4; j++) o[t][j] = 0.f;

    const int nkb = 2 * qb + 2;
    for (int kb = 0; kb < nkb; kb++) {
        if (kb + 1 < nkb) { load_kv(kb + 1, (kb + 1) & 1); CPC(); CPW(1); }
        else              { CPW(0); }
        __syncthreads();

        const float* Ks = Ksb[kb & 1];
        const float* Vs = Vsb[kb & 1];
        const int kBase = kb * 64;

        // ---- S = Q K^T ----
        float sfrag[8][4];
#pragma unroll
        for (int t = 0; t < 8; t++)
#pragma unroll
            for (int j = 0; j < 4; j++) sfrag[t][j] = 0.f;

#pragma unroll
        for (int kk = 0; kk < 64; kk += 8) {
            uint32_t a[4];
            int ar = (w << 4) + (lane >> 2);
            int ac = kk + (lane & 3);
            a[0] = __float_as_uint(Qs[ar * 68 + ac]);
            a[1] = __float_as_uint(Qs[(ar + 8) * 68 + ac]);
            a[2] = __float_as_uint(Qs[ar * 68 + ac + 4]);
            a[3] = __float_as_uint(Qs[(ar + 8) * 68 + ac + 4]);
#pragma unroll
            for (int t = 0; t < 8; t++) {
                int br = t * 8 + (lane >> 2);
                uint32_t b0 = __float_as_uint(Ks[br * 68 + ac]);
                uint32_t b1 = __float_as_uint(Ks[br * 68 + ac + 4]);
                mma_tf32(sfrag[t], a, b0, b1);
            }
        }

        // ---- scale + causal mask -> Ps ----
        {
            int r0 = (w << 4) + (lane >> 2);
            int r1 = r0 + 8;
            int qg0 = qBase + r0, qg1 = qBase + r1;
#pragma unroll
            for (int t = 0; t < 8; t++) {
                int c = t * 8 + 2 * (lane & 3);
                int kg = kBase + c;
                float v0 = sfrag[t][0] * scale; if (kg     > qg0) v0 = -1e30f;
                float v1 = sfrag[t][1] * scale; if (kg + 1 > qg0) v1 = -1e30f;
                float v2 = sfrag[t][2] * scale; if (kg     > qg1) v2 = -1e30f;
                float v3 = sfrag[t][3] * scale; if (kg + 1 > qg1) v3 = -1e30f;
                *(float2*)&Ps[r0 * 68 + c] = make_float2(v0, v1);
                *(float2*)&Ps[r1 * 68 + c] = make_float2(v2, v3);
            }
        }
        __syncwarp();

        // ---- online softmax: 2 lanes per row ----
        {
            int srow = (w << 4) + (lane >> 1);
            int half = lane & 1;
            float* prow = &Ps[srow * 68 + half * 32];
            float mx = -1e30f;
#pragma unroll 8
            for (int c = 0; c < 32; c++) mx = fmaxf(mx, prow[c]);
            mx = fmaxf(mx, __shfl_xor_sync(0xffffffffu, mx, 1));
            float mold = mrow[srow];
            float mnew = fmaxf(mold, mx);
            float sum = 0.f;
#pragma unroll 8
            for (int c = 0; c < 32; c++) {
                float p = tf32r(__expf(prow[c] - mnew));
                prow[c] = p;
                sum += p;
            }
            sum += __shfl_xor_sync(0xffffffffu, sum, 1);
            if (!half) {
                float alpha = __expf(mold - mnew);
                arow[srow] = alpha;
                mrow[srow] = mnew;
                lrow[srow] = lrow[srow] * alpha + sum;
            }
        }
        __syncwarp();

        // ---- O = alpha*O + P V ----
        {
            float a0 = arow[(w << 4) + (lane >> 2)];
            float a1 = arow[(w << 4) + (lane >> 2) + 8];
#pragma unroll
            for (int t = 0; t < 8; t++) {
                o[t][0] *= a0; o[t][1] *= a0;
                o[t][2] *= a1; o[t][3] *= a1;
            }
#pragma unroll
            for (int kk = 0; kk < 64; kk += 8) {
                uint32_t a[4];
                int ar = (w << 4) + (lane >> 2);
                int ac = kk + (lane & 3);
                a[0] = __float_as_uint(Ps[ar * 68 + ac]);
                a[1] = __float_as_uint(Ps[(ar + 8) * 68 + ac]);
                a[2] = __float_as_uint(Ps[ar * 68 + ac + 4]);
                a[3] = __float_as_uint(Ps[(ar + 8) * 68 + ac + 4]);
#pragma unroll
                for (int t = 0; t < 8; t++) {
                    int bn = t * 8 + (lane >> 2);
                    uint32_t b0 = __float_as_uint(Vs[(ac) * 72 + bn]);
                    uint32_t b1 = __float_as_uint(Vs[(ac + 4) * 72 + bn]);
                    mma_tf32(o[t], a, b0, b1);
                }
            }
        }
        __syncthreads();   // protect K/V buffer reuse next iteration
    }

    // ---- normalize + write out (rounded for downstream Wo GEMM) ----
    {
        int r0 = (w << 4) + (lane >> 2);
        float inv0 = 1.f / lrow[r0];
        float inv1 = 1.f / lrow[r0 + 8];
        int gr0 = qBase + r0;
#pragma unroll
        for (int t = 0; t < 8; t++) {
            int c = hoff + t * 8 + 2 * (lane & 3);
            *(float2*)&O[gr0 * HID + c] =
                make_float2(tf32r(o[t][0] * inv0), tf32r(o[t][1] * inv0));
            *(float2*)&O[(gr0 + 8) * HID + c] =
                make_float2(tf32r(o[t][2] * inv1), tf32r(o[t][3] * inv1));
        }
    }
}

// ---------------------------------------------------------------------------
// Host launcher. Inputs: 0:X 1:position_ids 2:mask(unused) 3:Wq 4:Wk 5:Wv
//                        6:Wo 7:bo ; output f32[1,4096,1024]
// ---------------------------------------------------------------------------
extern "C" void kernel_launch(void* const* d_in, const int* in_sizes, int n_in,
                              void* d_out, int out_size) {
    const float* X  = (const float*)d_in[0];
    const int* pos  = (const int*)d_in[1];
    const float* Wq = (const float*)d_in[3];
    const float* Wk = (const float*)d_in[4];
    const float* Wv = (const float*)d_in[5];
    const float* Wo = (const float*)d_in[6];
    const float* bo = (const float*)d_in[7];
    float* out = (float*)d_out;

    float *Qd, *Kd, *Vd, *Cd, *Xr, *Wqr, *Wkr, *Wvr, *Wor;
    cudaGetSymbolAddress((void**)&Qd, g_Q);
    cudaGetSymbolAddress((void**)&Kd, g_K);
    cudaGetSymbolAddress((void**)&Vd, g_V);
    cudaGetSymbolAddress((void**)&Cd, g_C);
    cudaGetSymbolAddress((void**)&Xr, g_Xr);
    cudaGetSymbolAddress((void**)&Wqr, g_Wqr);
    cudaGetSymbolAddress((void**)&Wkr, g_Wkr);
    cudaGetSymbolAddress((void**)&Wvr, g_Wvr);
    cudaGetSymbolAddress((void**)&Wor, g_Wor);

    // pre-round operands to tf32
    const int nX4 = SEQ * HID / 4, nW4 = HID * HID / 4;
    round_tf32_kernel<<<(nX4 + 255) / 256, 256>>>((const float4*)X, (float4*)Xr, nX4);
    round_tf32_kernel<<<(nW4 + 255) / 256, 256>>>((const float4*)Wq, (float4*)Wqr, nW4);
    round_tf32_kernel<<<(nW4 + 255) / 256, 256>>>((const float4*)Wk, (float4*)Wkr, nW4);
    round_tf32_kernel<<<(nW4 + 255) / 256, 256>>>((const float4*)Wv, (float4*)Wvr, nW4);
    round_tf32_kernel<<<(nW4 + 255) / 256, 256>>>((const float4*)Wo, (float4*)Wor, nW4);

    dim3 ggrid(HID / 128, SEQ / 128);  // (8, 32)
    const int gemm_smem = 4608 * 4 * (int)sizeof(float);  // 73728 B

    cudaFuncSetAttribute(gemm_tf32<false, true>,
                         cudaFuncAttributeMaxDynamicSharedMemorySize, gemm_smem);
    cudaFuncSetAttribute(gemm_tf32<false, false>,
                         cudaFuncAttributeMaxDynamicSharedMemorySize, gemm_smem);
    cudaFuncSetAttribute(gemm_tf32<true, false>,
                         cudaFuncAttributeMaxDynamicSharedMemorySize, gemm_smem);

    gemm_tf32<false, true><<<ggrid, 256, gemm_smem>>>(Xr, Wqr, nullptr, pos, Qd, SEQ, HID, HID);
    gemm_tf32<false, true><<<ggrid, 256, gemm_smem>>>(Xr, Wkr, nullptr, pos, Kd, SEQ, HID, HID);
    gemm_tf32<false, false><<<ggrid, 256, gemm_smem>>>(Xr, Wvr, nullptr, nullptr, Vd, SEQ, HID, HID);

    const int flash_smem = 35712 * (int)sizeof(float);    // 142848 B
    cudaFuncSetAttribute(flash_attn, cudaFuncAttributeMaxDynamicSharedMemorySize, flash_smem);
    flash_attn<<<dim3(SEQ / 128, NH), 256, flash_smem>>>(Qd, Kd, Vd, Cd);

    gemm_tf32<true, false><<<ggrid, 256, gemm_smem>>>(Cd, Wor, bo, nullptr, out, SEQ, HID, HID);
}

// round 8
// speedup vs baseline: 1.0927x; 1.0927x over previous
#include <cuda_runtime.h>
#include <math.h>
#include <stdint.h>

#define SEQ 4096
#define HID 1024
#define NH  16
#define HD  64

// Scratch (allocation-free rule: __device__ globals)
__device__ float g_Q[SEQ * HID];
__device__ float g_K[SEQ * HID];
__device__ float g_V[SEQ * HID];
__device__ float g_C[SEQ * HID];
__device__ float g_Xr[SEQ * HID];
__device__ float g_Wqr[HID * HID];
__device__ float g_Wkr[HID * HID];
__device__ float g_Wvr[HID * HID];
__device__ float g_Wor[HID * HID];

// ---------------------------------------------------------------------------
// helpers
// ---------------------------------------------------------------------------
__device__ __forceinline__ float tf32r(float x) {
    uint32_t u;
    asm("cvt.rna.tf32.f32 %0, %1;" : "=r"(u) : "f"(x));
    return __uint_as_float(u);
}

__device__ __forceinline__ void mma_tf32(float (&d)[4], const uint32_t (&a)[4],
                                         uint32_t b0, uint32_t b1) {
    asm volatile(
        "mma.sync.aligned.m16n8k8.row.col.f32.tf32.tf32.f32 "
        "{%0,%1,%2,%3}, {%4,%5,%6,%7}, {%8,%9}, {%0,%1,%2,%3};\n"
        : "+f"(d[0]), "+f"(d[1]), "+f"(d[2]), "+f"(d[3])
        : "r"(a[0]), "r"(a[1]), "r"(a[2]), "r"(a[3]), "r"(b0), "r"(b1));
}

__device__ __forceinline__ uint32_t sptr(const void* p) {
    return (uint32_t)__cvta_generic_to_shared(p);
}
#define CPA16(dst, src) \
    asm volatile("cp.async.cg.shared.global [%0], [%1], 16;" :: "r"(dst), "l"(src))
#define CPC() asm volatile("cp.async.commit_group;")
#define CPW(N) asm volatile("cp.async.wait_group %0;" :: "n"(N))

// ---------------------------------------------------------------------------
// tf32 pre-rounding: all 5 tensors in ONE launch.
// Segments (in 256-thread blocks of float4): X:4096, then 4 weights of 1024.
// ---------------------------------------------------------------------------
__global__ void round_all_kernel(const float4* __restrict__ X, float4* __restrict__ Xr,
                                 const float4* __restrict__ W0, float4* __restrict__ W0r,
                                 const float4* __restrict__ W1, float4* __restrict__ W1r,
                                 const float4* __restrict__ W2, float4* __restrict__ W2r,
                                 const float4* __restrict__ W3, float4* __restrict__ W3r) {
    int b = blockIdx.x;
    const float4* src;
    float4* dst;
    int off;
    if (b < 4096)      { src = X;  dst = Xr;  off = b * 256; }
    else if (b < 5120) { src = W0; dst = W0r; off = (b - 4096) * 256; }
    else if (b < 6144) { src = W1; dst = W1r; off = (b - 5120) * 256; }
    else if (b < 7168) { src = W2; dst = W2r; off = (b - 6144) * 256; }
    else               { src = W3; dst = W3r; off = (b - 7168) * 256; }
    int i = off + threadIdx.x;
    float4 v = src[i];
    dst[i] = make_float4(tf32r(v.x), tf32r(v.y), tf32r(v.z), tf32r(v.w));
}

// ---------------------------------------------------------------------------
// tf32 GEMM: C[M,N] = A[M,K] @ B[N,K]^T. Operands pre-rounded in gmem.
// 2-stage cp.async pipeline, BM=BN=128, BK=32, 256 threads, 8 warps 4x2.
// Smem pitch 36 floats -> conflict-free LDS, 16B-aligned rows for cp.async.
// ROPE: rotary on output pairs (t, t+4) in registers. !BIAS => round output.
// ---------------------------------------------------------------------------
template <bool BIAS, bool ROPE>
__global__ __launch_bounds__(256, 2)
void gemm_tf32(const float* __restrict__ A, const float* __restrict__ B,
               const float* __restrict__ bias, const int* __restrict__ pos,
               float* __restrict__ C, int M, int N, int K) {
    extern __shared__ float smem[];
    float* Asb[2] = {smem, smem + 4608};
    float* Bsb[2] = {smem + 9216, smem + 13824};

    const int tid = threadIdx.x;
    const int lane = tid & 31;
    const int w = tid >> 5;
    const int wm = w & 3;
    const int wn = w >> 2;
    const int rowBase = blockIdx.y * 128;
    const int colBase = blockIdx.x * 128;

    float acc[16][4];
#pragma unroll
    for (int i = 0; i < 16; i++)
#pragma unroll
        for (int j = 0; j < 4; j++) acc[i][j] = 0.f;

    const int ldrow = tid >> 1;
    const int ldcol = (tid & 1) * 16;

    auto load_stage = [&](int k0, int buf) {
        const float* Ag = &A[(rowBase + ldrow) * K + k0 + ldcol];
        const float* Bg = &B[(colBase + ldrow) * K + k0 + ldcol];
        uint32_t da = sptr(&Asb[buf][ldrow * 36 + ldcol]);
        uint32_t db = sptr(&Bsb[buf][ldrow * 36 + ldcol]);
#pragma unroll
        for (int i = 0; i < 4; i++) {
            CPA16(da + i * 16, Ag + i * 4);
            CPA16(db + i * 16, Bg + i * 4);
        }
    };

    load_stage(0, 0);
    CPC();

    const int NK = K / 32;
    for (int s = 0; s < NK; s++) {
        if (s + 1 < NK) { load_stage((s + 1) * 32, (s + 1) & 1); CPC(); CPW(1); }
        else            { CPW(0); }
        __syncthreads();

        const float* As = Asb[s & 1];
        const float* Bs = Bsb[s & 1];
#pragma unroll
        for (int kk = 0; kk < 32; kk += 8) {
            uint32_t a[2][4];
#pragma unroll
            for (int mt = 0; mt < 2; mt++) {
                int ar = wm * 32 + mt * 16 + (lane >> 2);
                int ac = kk + (lane & 3);
                a[mt][0] = __float_as_uint(As[ar * 36 + ac]);
                a[mt][1] = __float_as_uint(As[(ar + 8) * 36 + ac]);
                a[mt][2] = __float_as_uint(As[ar * 36 + ac + 4]);
                a[mt][3] = __float_as_uint(As[(ar + 8) * 36 + ac + 4]);
            }
#pragma unroll
            for (int t = 0; t < 8; t++) {
                int br = wn * 64 + t * 8 + (lane >> 2);
                int bc = kk + (lane & 3);
                uint32_t b0 = __float_as_uint(Bs[br * 36 + bc]);
                uint32_t b1 = __float_as_uint(Bs[br * 36 + bc + 4]);
                mma_tf32(acc[t], a[0], b0, b1);
                mma_tf32(acc[8 + t], a[1], b0, b1);
            }
        }
        __syncthreads();
    }

    if (ROPE) {
        float th[8];
#pragma unroll
        for (int t = 0; t < 4; t++)
#pragma unroll
            for (int b = 0; b < 2; b++) {
                int j = t * 8 + 2 * (lane & 3) + b;
                th[t * 2 + b] = expf(-(float)j * (9.210340371976184f / 32.0f));
            }
#pragma unroll
        for (int mt = 0; mt < 2; mt++) {
            int r0 = rowBase + wm * 32 + mt * 16 + (lane >> 2);
            float p0 = (float)pos[r0];
            float p1 = (float)pos[r0 + 8];
#pragma unroll
            for (int t = 0; t < 4; t++) {
#pragma unroll
                for (int jj = 0; jj < 4; jj++) {
                    float pv = (jj < 2) ? p0 : p1;
                    float sn, cs;
                    sincosf(pv * th[t * 2 + (jj & 1)], &sn, &cs);
                    float x1 = acc[mt * 8 + t][jj];
                    float x2 = acc[mt * 8 + t + 4][jj];
                    acc[mt * 8 + t][jj]     = x1 * cs - x2 * sn;
                    acc[mt * 8 + t + 4][jj] = x1 * sn + x2 * cs;
                }
            }
        }
    }

#pragma unroll
    for (int mt = 0; mt < 2; mt++) {
#pragma unroll
        for (int t = 0; t < 8; t++) {
            int r0 = rowBase + wm * 32 + mt * 16 + (lane >> 2);
            int c0 = colBase + wn * 64 + t * 8 + 2 * (lane & 3);
            float* d = acc[mt * 8 + t];
            float v0 = d[0], v1 = d[1], v2 = d[2], v3 = d[3];
            if (BIAS) {
                float bb0 = bias[c0], bb1 = bias[c0 + 1];
                v0 += bb0; v1 += bb1; v2 += bb0; v3 += bb1;
            } else {
                v0 = tf32r(v0); v1 = tf32r(v1); v2 = tf32r(v2); v3 = tf32r(v3);
            }
            *(float2*)&C[r0 * N + c0] = make_float2(v0, v1);
            *(float2*)&C[(r0 + 8) * N + c0] = make_float2(v2, v3);
        }
    }
}

// ---------------------------------------------------------------------------
// Causal flash attention, tf32 MMA, single-buffered K/V via cp.async.
// BR=128, BC=64. smem = 107,008 B -> 2 CTAs/SM (the round-5 double-buffer
// variant dropped to 1 CTA/SM and regressed).
// Qs/Ks/Ps pitch 68; Vs pitch 72. Inputs pre-rounded tf32; output rounded.
// ---------------------------------------------------------------------------
__global__ __launch_bounds__(256, 2)
void flash_attn(const float* __restrict__ Q, const float* __restrict__ K,
                const float* __restrict__ V, float* __restrict__ O) {
    extern __shared__ float sm[];
    float* Qs = sm;                    // 128 x 68 = 8704
    float* Ks = sm + 8704;             // 64 x 68  = 4352
    float* Vs = sm + 13056;            // 64 x 72  = 4608
    float* Ps = sm + 17664;            // 128 x 68 = 8704
    float* mrow = sm + 26368;          // 128
    float* lrow = mrow + 128;          // 128
    float* arow = lrow + 128;          // 128  (total 26752 floats = 107008 B)

    const int tid = threadIdx.x;
    const int lane = tid & 31;
    const int w = tid >> 5;
    const int qb = gridDim.x - 1 - blockIdx.x;   // heavy blocks first
    const int h = blockIdx.y;
    const int qBase = qb * 128;
    const int hoff = h * HD;
    const float scale = 0.125f;

    auto load_kv = [&](int kb) {
        const int kBase = kb * 64;
        for (int i = tid; i < 2048; i += 256) {
            if (i < 1024) {
                int r = i >> 4, ch = (i & 15) * 4;
                CPA16(sptr(&Ks[r * 68 + ch]), &K[(kBase + r) * HID + hoff + ch]);
            } else {
                int i2 = i - 1024;
                int r = i2 >> 4, ch = (i2 & 15) * 4;
                CPA16(sptr(&Vs[r * 72 + ch]), &V[(kBase + r) * HID + hoff + ch]);
            }
        }
    };

    // stage Q (once)
    for (int i = tid; i < 2048; i += 256) {
        int r = i >> 4, ch = (i & 15) * 4;
        CPA16(sptr(&Qs[r * 68 + ch]), &Q[(qBase + r) * HID + hoff + ch]);
    }
    if (tid < 128) { mrow[tid] = -1e30f; lrow[tid] = 0.f; }

    float o[8][4];
#pragma unroll
    for (int t = 0; t < 8; t++)
#pragma unroll
        for (int j = 0; j < 4; j++) o[t][j] = 0.f;

    const int nkb = 2 * qb + 2;
    for (int kb = 0; kb < nkb; kb++) {
        load_kv(kb);
        CPC(); CPW(0);
        __syncthreads();   // K/V (and on kb=0, Q + stats) visible

        const int kBase = kb * 64;

        // ---- S = Q K^T ----
        float sfrag[8][4];
#pragma unroll
        for (int t = 0; t < 8; t++)
#pragma unroll
            for (int j = 0; j < 4; j++) sfrag[t][j] = 0.f;

#pragma unroll
        for (int kk = 0; kk < 64; kk += 8) {
            uint32_t a[4];
            int ar = (w << 4) + (lane >> 2);
            int ac = kk + (lane & 3);
            a[0] = __float_as_uint(Qs[ar * 68 + ac]);
            a[1] = __float_as_uint(Qs[(ar + 8) * 68 + ac]);
            a[2] = __float_as_uint(Qs[ar * 68 + ac + 4]);
            a[3] = __float_as_uint(Qs[(ar + 8) * 68 + ac + 4]);
#pragma unroll
            for (int t = 0; t < 8; t++) {
                int br = t * 8 + (lane >> 2);
                uint32_t b0 = __float_as_uint(Ks[br * 68 + ac]);
                uint32_t b1 = __float_as_uint(Ks[br * 68 + ac + 4]);
                mma_tf32(sfrag[t], a, b0, b1);
            }
        }

        // ---- scale + causal mask -> Ps ----
        {
            int r0 = (w << 4) + (lane >> 2);
            int r1 = r0 + 8;
            int qg0 = qBase + r0, qg1 = qBase + r1;
#pragma unroll
            for (int t = 0; t < 8; t++) {
                int c = t * 8 + 2 * (lane & 3);
                int kg = kBase + c;
                float v0 = sfrag[t][0] * scale; if (kg     > qg0) v0 = -1e30f;
                float v1 = sfrag[t][1] * scale; if (kg + 1 > qg0) v1 = -1e30f;
                float v2 = sfrag[t][2] * scale; if (kg     > qg1) v2 = -1e30f;
                float v3 = sfrag[t][3] * scale; if (kg + 1 > qg1) v3 = -1e30f;
                *(float2*)&Ps[r0 * 68 + c] = make_float2(v0, v1);
                *(float2*)&Ps[r1 * 68 + c] = make_float2(v2, v3);
            }
        }
        __syncwarp();

        // ---- online softmax: 2 lanes per row ----
        {
            int srow = (w << 4) + (lane >> 1);
            int half = lane & 1;
            float* prow = &Ps[srow * 68 + half * 32];
            float mx = -1e30f;
#pragma unroll 8
            for (int c = 0; c < 32; c++) mx = fmaxf(mx, prow[c]);
            mx = fmaxf(mx, __shfl_xor_sync(0xffffffffu, mx, 1));
            float mold = mrow[srow];
            float mnew = fmaxf(mold, mx);
            float sum = 0.f;
#pragma unroll 8
            for (int c = 0; c < 32; c++) {
                float p = tf32r(__expf(prow[c] - mnew));
                prow[c] = p;
                sum += p;
            }
            sum += __shfl_xor_sync(0xffffffffu, sum, 1);
            if (!half) {
                float alpha = __expf(mold - mnew);
                arow[srow] = alpha;
                mrow[srow] = mnew;
                lrow[srow] = lrow[srow] * alpha + sum;
            }
        }
        __syncwarp();

        // ---- O = alpha*O + P V ----
        {
            float a0 = arow[(w << 4) + (lane >> 2)];
            float a1 = arow[(w << 4) + (lane >> 2) + 8];
#pragma unroll
            for (int t = 0; t < 8; t++) {
                o[t][0] *= a0; o[t][1] *= a0;
                o[t][2] *= a1; o[t][3] *= a1;
            }
#pragma unroll
            for (int kk = 0; kk < 64; kk += 8) {
                uint32_t a[4];
                int ar = (w << 4) + (lane >> 2);
                int ac = kk + (lane & 3);
                a[0] = __float_as_uint(Ps[ar * 68 + ac]);
                a[1] = __float_as_uint(Ps[(ar + 8) * 68 + ac]);
                a[2] = __float_as_uint(Ps[ar * 68 + ac + 4]);
                a[3] = __float_as_uint(Ps[(ar + 8) * 68 + ac + 4]);
#pragma unroll
                for (int t = 0; t < 8; t++) {
                    int bn = t * 8 + (lane >> 2);
                    uint32_t b0 = __float_as_uint(Vs[(ac) * 72 + bn]);
                    uint32_t b1 = __float_as_uint(Vs[(ac + 4) * 72 + bn]);
                    mma_tf32(o[t], a, b0, b1);
                }
            }
        }
        __syncthreads();   // protect K/V restage next iteration
    }

    // ---- normalize + write out (rounded for downstream Wo GEMM) ----
    {
        int r0 = (w << 4) + (lane >> 2);
        float inv0 = 1.f / lrow[r0];
        float inv1 = 1.f / lrow[r0 + 8];
        int gr0 = qBase + r0;
#pragma unroll
        for (int t = 0; t < 8; t++) {
            int c = hoff + t * 8 + 2 * (lane & 3);
            *(float2*)&O[gr0 * HID + c] =
                make_float2(tf32r(o[t][0] * inv0), tf32r(o[t][1] * inv0));
            *(float2*)&O[(gr0 + 8) * HID + c] =
                make_float2(tf32r(o[t][2] * inv1), tf32r(o[t][3] * inv1));
        }
    }
}

// ---------------------------------------------------------------------------
// Host launcher. Inputs: 0:X 1:position_ids 2:mask(unused) 3:Wq 4:Wk 5:Wv
//                        6:Wo 7:bo ; output f32[1,4096,1024]
// ---------------------------------------------------------------------------
extern "C" void kernel_launch(void* const* d_in, const int* in_sizes, int n_in,
                              void* d_out, int out_size) {
    const float* X  = (const float*)d_in[0];
    const int* pos  = (const int*)d_in[1];
    const float* Wq = (const float*)d_in[3];
    const float* Wk = (const float*)d_in[4];
    const float* Wv = (const float*)d_in[5];
    const float* Wo = (const float*)d_in[6];
    const float* bo = (const float*)d_in[7];
    float* out = (float*)d_out;

    float *Qd, *Kd, *Vd, *Cd, *Xr, *Wqr, *Wkr, *Wvr, *Wor;
    cudaGetSymbolAddress((void**)&Qd, g_Q);
    cudaGetSymbolAddress((void**)&Kd, g_K);
    cudaGetSymbolAddress((void**)&Vd, g_V);
    cudaGetSymbolAddress((void**)&Cd, g_C);
    cudaGetSymbolAddress((void**)&Xr, g_Xr);
    cudaGetSymbolAddress((void**)&Wqr, g_Wqr);
    cudaGetSymbolAddress((void**)&Wkr, g_Wkr);
    cudaGetSymbolAddress((void**)&Wvr, g_Wvr);
    cudaGetSymbolAddress((void**)&Wor, g_Wor);

    // pre-round all operands to tf32 in one launch (8192 blocks)
    round_all_kernel<<<8192, 256>>>(
        (const float4*)X, (float4*)Xr,
        (const float4*)Wq, (float4*)Wqr,
        (const float4*)Wk, (float4*)Wkr,
        (const float4*)Wv, (float4*)Wvr,
        (const float4*)Wo, (float4*)Wor);

    dim3 ggrid(HID / 128, SEQ / 128);  // (8, 32)
    const int gemm_smem = 4608 * 4 * (int)sizeof(float);  // 73728 B

    cudaFuncSetAttribute(gemm_tf32<false, true>,
                         cudaFuncAttributeMaxDynamicSharedMemorySize, gemm_smem);
    cudaFuncSetAttribute(gemm_tf32<false, false>,
                         cudaFuncAttributeMaxDynamicSharedMemorySize, gemm_smem);
    cudaFuncSetAttribute(gemm_tf32<true, false>,
                         cudaFuncAttributeMaxDynamicSharedMemorySize, gemm_smem);

    gemm_tf32<false, true><<<ggrid, 256, gemm_smem>>>(Xr, Wqr, nullptr, pos, Qd, SEQ, HID, HID);
    gemm_tf32<false, true><<<ggrid, 256, gemm_smem>>>(Xr, Wkr, nullptr, pos, Kd, SEQ, HID, HID);
    gemm_tf32<false, false><<<ggrid, 256, gemm_smem>>>(Xr, Wvr, nullptr, nullptr, Vd, SEQ, HID, HID);

    const int flash_smem = 26752 * (int)sizeof(float);    // 107008 B
    cudaFuncSetAttribute(flash_attn, cudaFuncAttributeMaxDynamicSharedMemorySize, flash_smem);
    flash_attn<<<dim3(SEQ / 128, NH), 256, flash_smem>>>(Qd, Kd, Vd, Cd);

    gemm_tf32<true, false><<<ggrid, 256, gemm_smem>>>(Cd, Wor, bo, nullptr, out, SEQ, HID, HID);
}

// round 10
// speedup vs baseline: 2.8355x; 2.5951x over previous
#include <cuda_runtime.h>
#include <cuda_fp16.h>
#include <math.h>
#include <stdint.h>

#define SEQ 4096
#define HID 1024
#define NH  16
#define HD  64

// Scratch (allocation-free rule: __device__ globals), all fp16
__device__ __half g_Xh[SEQ * HID];
__device__ __half g_Wqh[HID * HID];
__device__ __half g_Wkh[HID * HID];
__device__ __half g_Wvh[HID * HID];
__device__ __half g_Woh[HID * HID];
__device__ __half g_Qh[SEQ * HID];
__device__ __half g_Kh[SEQ * HID];
__device__ __half g_Vh[SEQ * HID];
__device__ __half g_Vth[SEQ * HID];   // per-head transposed V: [h][d][s]
__device__ __half g_Ch[SEQ * HID];

// ---------------------------------------------------------------------------
// helpers
// ---------------------------------------------------------------------------
__device__ __forceinline__ uint32_t sptr(const void* p) {
    return (uint32_t)__cvta_generic_to_shared(p);
}
#define CPA16(dst, src) \
    asm volatile("cp.async.cg.shared.global [%0], [%1], 16;" :: "r"(dst), "l"(src))
#define CPC() asm volatile("cp.async.commit_group;")
#define CPW(N) asm volatile("cp.async.wait_group %0;" :: "n"(N))

__device__ __forceinline__ void mma_h(float (&d)[4], uint32_t a0, uint32_t a1,
                                      uint32_t a2, uint32_t a3,
                                      uint32_t b0, uint32_t b1) {
    asm volatile(
        "mma.sync.aligned.m16n8k16.row.col.f32.f16.f16.f32 "
        "{%0,%1,%2,%3}, {%4,%5,%6,%7}, {%8,%9}, {%0,%1,%2,%3};\n"
        : "+f"(d[0]), "+f"(d[1]), "+f"(d[2]), "+f"(d[3])
        : "r"(a0), "r"(a1), "r"(a2), "r"(a3), "r"(b0), "r"(b1));
}

__device__ __forceinline__ uint32_t packh2(float lo, float hi) {
    __half2 h = __floats2half2_rn(lo, hi);
    return *reinterpret_cast<uint32_t*>(&h);
}

// ---------------------------------------------------------------------------
// f32 -> fp16 pack, all 5 tensors in one launch.
// blocks: X:4096, Wq/Wk/Wv/Wo: 1024 each. 256 thr x 4 elems.
// ---------------------------------------------------------------------------
__global__ void pack_all_kernel(const float4* __restrict__ X, __half* __restrict__ Xh,
                                const float4* __restrict__ W0, __half* __restrict__ W0h,
                                const float4* __restrict__ W1, __half* __restrict__ W1h,
                                const float4* __restrict__ W2, __half* __restrict__ W2h,
                                const float4* __restrict__ W3, __half* __restrict__ W3h) {
    int b = blockIdx.x;
    const float4* src;
    __half* dst;
    int off;
    if (b < 4096)      { src = X;  dst = Xh;  off = b * 256; }
    else if (b < 5120) { src = W0; dst = W0h; off = (b - 4096) * 256; }
    else if (b < 6144) { src = W1; dst = W1h; off = (b - 5120) * 256; }
    else if (b < 7168) { src = W2; dst = W2h; off = (b - 6144) * 256; }
    else               { src = W3; dst = W3h; off = (b - 7168) * 256; }
    int i = off + threadIdx.x;
    float4 v = src[i];
    uint2 o;
    o.x = packh2(v.x, v.y);
    o.y = packh2(v.z, v.w);
    *(uint2*)&dst[i * 4] = o;
}

// ---------------------------------------------------------------------------
// fp16 GEMM: C[M,N] = A[M,K] @ B[N,K]^T, f32 accum. BM=BN=128, BK=64 halves,
// 256 threads = 8 warps (4m x 2n), warp tile 32x64, m16n8k16.
// smem pitch 72 halves (144 B rows, 16B-aligned) -> conflict-free frag LDS.
// 2-stage cp.async pipeline (structure proven in round 8).
// MODE: 0 = plain -> half (V); 1 = RoPE -> half (Q,K); 2 = +bias -> f32 (out).
// ---------------------------------------------------------------------------
template <int MODE, typename OutT>
__global__ __launch_bounds__(256, 2)
void gemm_h(const __half* __restrict__ A, const __half* __restrict__ B,
            const float* __restrict__ bias, const int* __restrict__ pos,
            OutT* __restrict__ C, int M, int N, int K) {
    extern __shared__ char smem[];
    __half* Ab[2] = {(__half*)smem, (__half*)(smem + 36864)};
    __half* Bb[2] = {(__half*)(smem + 18432), (__half*)(smem + 55296)};

    const int tid = threadIdx.x;
    const int lane = tid & 31;
    const int w = tid >> 5;
    const int wm = w & 3;
    const int wn = w >> 2;
    const int g = lane >> 2;     // group row
    const int q = lane & 3;      // in-group
    const int rowBase = blockIdx.y * 128;
    const int colBase = blockIdx.x * 128;

    float acc[16][4];
#pragma unroll
    for (int i = 0; i < 16; i++)
#pragma unroll
        for (int j = 0; j < 4; j++) acc[i][j] = 0.f;

    // stage: 2048 x 16B chunks (A: 128 rows x 8, B: same)
    auto stage = [&](int k0, int buf) {
        __half* As = Ab[buf];
        __half* Bs = Bb[buf];
#pragma unroll
        for (int t = 0; t < 8; t++) {
            int i = tid + t * 256;
            int mat = i >> 10;
            int r = (i >> 3) & 127;
            int ch = i & 7;
            const __half* src = mat ? &B[(colBase + r) * K + k0 + ch * 8]
                                    : &A[(rowBase + r) * K + k0 + ch * 8];
            uint32_t d = sptr(mat ? &Bs[r * 72] : &As[r * 72]) + ch * 16;
            CPA16(d, src);
        }
    };

    stage(0, 0);
    CPC();

    const int NK = K / 64;   // 16
    for (int s = 0; s < NK; s++) {
        if (s + 1 < NK) { stage((s + 1) * 64, (s + 1) & 1); CPC(); CPW(1); }
        else            { CPW(0); }
        __syncthreads();

        const __half* As = Ab[s & 1];
        const __half* Bs = Bb[s & 1];
#pragma unroll
        for (int kg = 0; kg < 4; kg++) {     // 4 x k16
            uint32_t a[2][4];
#pragma unroll
            for (int mt = 0; mt < 2; mt++) {
                int ar = wm * 32 + mt * 16 + g;
                const __half* p0 = &As[ar * 72 + kg * 16 + 2 * q];
                const __half* p1 = &As[(ar + 8) * 72 + kg * 16 + 2 * q];
                a[mt][0] = *(const uint32_t*)p0;
                a[mt][1] = *(const uint32_t*)p1;
                a[mt][2] = *(const uint32_t*)(p0 + 8);
                a[mt][3] = *(const uint32_t*)(p1 + 8);
            }
#pragma unroll
            for (int nt = 0; nt < 8; nt++) {
                int bn = wn * 64 + nt * 8 + g;
                const __half* pb = &Bs[bn * 72 + kg * 16 + 2 * q];
                uint32_t b0 = *(const uint32_t*)pb;
                uint32_t b1 = *(const uint32_t*)(pb + 8);
                mma_h(acc[nt], a[0][0], a[0][1], a[0][2], a[0][3], b0, b1);
                mma_h(acc[8 + nt], a[1][0], a[1][1], a[1][2], a[1][3], b0, b1);
            }
        }
        __syncthreads();
    }

    if (MODE == 1) {
        // RoPE: warp n-slab (64 cols) = one head; partner tiles (t, t+4).
        float th[8];
#pragma unroll
        for (int t = 0; t < 4; t++)
#pragma unroll
            for (int b = 0; b < 2; b++) {
                int j = t * 8 + 2 * q + b;
                th[t * 2 + b] = expf(-(float)j * (9.210340371976184f / 32.0f));
            }
#pragma unroll
        for (int mt = 0; mt < 2; mt++) {
            int r0 = rowBase + wm * 32 + mt * 16 + g;
            float p0 = (float)pos[r0];
            float p1 = (float)pos[r0 + 8];
#pragma unroll
            for (int t = 0; t < 4; t++) {
#pragma unroll
                for (int jj = 0; jj < 4; jj++) {
                    float pv = (jj < 2) ? p0 : p1;
                    float sn, cs;
                    sincosf(pv * th[t * 2 + (jj & 1)], &sn, &cs);
                    float x1 = acc[mt * 8 + t][jj];
                    float x2 = acc[mt * 8 + t + 4][jj];
                    acc[mt * 8 + t][jj]     = x1 * cs - x2 * sn;
                    acc[mt * 8 + t + 4][jj] = x1 * sn + x2 * cs;
                }
            }
        }
    }

#pragma unroll
    for (int mt = 0; mt < 2; mt++) {
#pragma unroll
        for (int t = 0; t < 8; t++) {
            int r0 = rowBase + wm * 32 + mt * 16 + g;
            int c0 = colBase + wn * 64 + t * 8 + 2 * q;
            float* d = acc[mt * 8 + t];
            if (MODE == 2) {
                float bb0 = bias[c0], bb1 = bias[c0 + 1];
                *(float2*)&((float*)C)[r0 * N + c0] = make_float2(d[0] + bb0, d[1] + bb1);
                *(float2*)&((float*)C)[(r0 + 8) * N + c0] = make_float2(d[2] + bb0, d[3] + bb1);
            } else {
                *(uint32_t*)&((__half*)C)[r0 * N + c0] = packh2(d[0], d[1]);
                *(uint32_t*)&((__half*)C)[(r0 + 8) * N + c0] = packh2(d[2], d[3]);
            }
        }
    }
}

// ---------------------------------------------------------------------------
// Per-head V transpose: Vt[h][d][s] = V[s][h*64+d]  (half).
// grid (SEQ/64, NH), 256 threads.
// ---------------------------------------------------------------------------
__global__ void transpose_v(const __half* __restrict__ V, __half* __restrict__ Vt) {
    __shared__ __half ts[64][72];
    const int tid = threadIdx.x;
    const int s0 = blockIdx.x * 64;
    const int h = blockIdx.y;
#pragma unroll
    for (int t = 0; t < 8; t++) {
        int i = tid + t * 256;              // 2048 half2
        int r = i >> 5, c2 = (i & 31) * 2;
        *(uint32_t*)&ts[r][c2] = *(const uint32_t*)&V[(s0 + r) * HID + h * 64 + c2];
    }
    __syncthreads();
#pragma unroll
    for (int t = 0; t < 8; t++) {
        int i = tid + t * 256;
        int d = i >> 5, s2 = (i & 31) * 2;
        __half2 v = __halves2half2(ts[s2][d], ts[s2 + 1][d]);
        *(uint32_t*)&Vt[(h * 64 + d) * SEQ + s0 + s2] = *reinterpret_cast<uint32_t*>(&v);
    }
}

// ---------------------------------------------------------------------------
// Causal flash attention, fp16 MMA (m16n8k16), f32 softmax/accum.
// BR=64, BC=64, 128 threads (4 warps x 16 rows). P stays in registers
// (C-frag == A-frag layout for fp16); m/l in registers (quad shfl).
// smem: Qs/Ks/Vs 64x72 halves = 27,648 B -> 4 CTAs/SM.
// ---------------------------------------------------------------------------
__global__ __launch_bounds__(128, 4)
void flash_h(const __half* __restrict__ Q, const __half* __restrict__ K,
             const __half* __restrict__ Vt, __half* __restrict__ O) {
    extern __shared__ char smem[];
    __half* Qs = (__half*)smem;              // 64 x 72
    __half* Ks = (__half*)(smem + 9216);     // 64 x 72
    __half* Vs = (__half*)(smem + 18432);    // 64 x 72 (d-major, k contiguous)

    const int tid = threadIdx.x;
    const int lane = tid & 31;
    const int w = tid >> 5;
    const int g = lane >> 2;
    const int q = lane & 3;
    const int qb = gridDim.x - 1 - blockIdx.x;   // heavy blocks first
    const int h = blockIdx.y;
    const int qBase = qb * 64;
    const int hoff = h * HD;
    const float scale = 0.125f;

    // stage Q tile (64 rows x 8 chunks)
#pragma unroll
    for (int t = 0; t < 4; t++) {
        int i = tid + t * 128;
        int r = i >> 3, ch = i & 7;
        CPA16(sptr(&Qs[r * 72]) + ch * 16, &Q[(qBase + r) * HID + hoff + ch * 8]);
    }

    float o[8][4];
#pragma unroll
    for (int t = 0; t < 8; t++)
#pragma unroll
        for (int j = 0; j < 4; j++) o[t][j] = 0.f;
    float m0 = -1e30f, m1 = -1e30f, l0 = 0.f, l1 = 0.f;

    const int r0q = qBase + w * 16 + g;     // global query rows of this thread
    const int r1q = r0q + 8;

    const int nkb = qb + 1;
    for (int kb = 0; kb < nkb; kb++) {
        const int kBase = kb * 64;
        // stage K (512 chunks) + Vt (512 chunks)
#pragma unroll
        for (int t = 0; t < 8; t++) {
            int i = tid + t * 128;
            int mat = i >> 9;
            int r = (i >> 3) & 63, ch = i & 7;
            if (mat == 0)
                CPA16(sptr(&Ks[r * 72]) + ch * 16, &K[(kBase + r) * HID + hoff + ch * 8]);
            else
                CPA16(sptr(&Vs[r * 72]) + ch * 16, &Vt[(h * 64 + r) * SEQ + kBase + ch * 8]);
        }
        CPC(); CPW(0);
        __syncthreads();

        // ---- S = Q K^T -> sfrag (f32) ----
        float sfrag[8][4];
#pragma unroll
        for (int t = 0; t < 8; t++)
#pragma unroll
            for (int j = 0; j < 4; j++) sfrag[t][j] = 0.f;

#pragma unroll
        for (int kg = 0; kg < 4; kg++) {
            int ar = w * 16 + g;
            const __half* p0 = &Qs[ar * 72 + kg * 16 + 2 * q];
            const __half* p1 = &Qs[(ar + 8) * 72 + kg * 16 + 2 * q];
            uint32_t a0 = *(const uint32_t*)p0;
            uint32_t a1 = *(const uint32_t*)p1;
            uint32_t a2 = *(const uint32_t*)(p0 + 8);
            uint32_t a3 = *(const uint32_t*)(p1 + 8);
#pragma unroll
            for (int nt = 0; nt < 8; nt++) {
                const __half* pb = &Ks[(nt * 8 + g) * 72 + kg * 16 + 2 * q];
                uint32_t b0 = *(const uint32_t*)pb;
                uint32_t b1 = *(const uint32_t*)(pb + 8);
                mma_h(sfrag[nt], a0, a1, a2, a3, b0, b1);
            }
        }

        // ---- scale (+ causal mask on the diagonal tile) ----
#pragma unroll
        for (int nt = 0; nt < 8; nt++) {
#pragma unroll
            for (int j = 0; j < 4; j++) sfrag[nt][j] *= scale;
        }
        if (kb == qb) {
#pragma unroll
            for (int nt = 0; nt < 8; nt++) {
                int c = kBase + nt * 8 + 2 * q;
                if (c     > r0q) sfrag[nt][0] = -1e30f;
                if (c + 1 > r0q) sfrag[nt][1] = -1e30f;
                if (c     > r1q) sfrag[nt][2] = -1e30f;
                if (c + 1 > r1q) sfrag[nt][3] = -1e30f;
            }
        }

        // ---- online softmax in registers (row stats via quad shfl) ----
        float mx0 = -1e30f, mx1 = -1e30f;
#pragma unroll
        for (int nt = 0; nt < 8; nt++) {
            mx0 = fmaxf(mx0, fmaxf(sfrag[nt][0], sfrag[nt][1]));
            mx1 = fmaxf(mx1, fmaxf(sfrag[nt][2], sfrag[nt][3]));
        }
        mx0 = fmaxf(mx0, __shfl_xor_sync(0xffffffffu, mx0, 1));
        mx0 = fmaxf(mx0, __shfl_xor_sync(0xffffffffu, mx0, 2));
        mx1 = fmaxf(mx1, __shfl_xor_sync(0xffffffffu, mx1, 1));
        mx1 = fmaxf(mx1, __shfl_xor_sync(0xffffffffu, mx1, 2));

        float mn0 = fmaxf(m0, mx0), mn1 = fmaxf(m1, mx1);
        float al0 = __expf(m0 - mn0), al1 = __expf(m1 - mn1);
        m0 = mn0; m1 = mn1;

        float s0 = 0.f, s1 = 0.f;
#pragma unroll
        for (int nt = 0; nt < 8; nt++) {
            sfrag[nt][0] = __expf(sfrag[nt][0] - m0);
            sfrag[nt][1] = __expf(sfrag[nt][1] - m0);
            sfrag[nt][2] = __expf(sfrag[nt][2] - m1);
            sfrag[nt][3] = __expf(sfrag[nt][3] - m1);
            s0 += sfrag[nt][0] + sfrag[nt][1];
            s1 += sfrag[nt][2] + sfrag[nt][3];
        }
        s0 += __shfl_xor_sync(0xffffffffu, s0, 1);
        s0 += __shfl_xor_sync(0xffffffffu, s0, 2);
        s1 += __shfl_xor_sync(0xffffffffu, s1, 1);
        s1 += __shfl_xor_sync(0xffffffffu, s1, 2);
        l0 = l0 * al0 + s0;
        l1 = l1 * al1 + s1;

#pragma unroll
        for (int t = 0; t < 8; t++) {
            o[t][0] *= al0; o[t][1] *= al0;
            o[t][2] *= al1; o[t][3] *= al1;
        }

        // ---- O += P V  (P C-frag packs directly into A-frag as half2) ----
#pragma unroll
        for (int kg = 0; kg < 4; kg++) {
            uint32_t a0 = packh2(sfrag[2 * kg][0], sfrag[2 * kg][1]);
            uint32_t a1 = packh2(sfrag[2 * kg][2], sfrag[2 * kg][3]);
            uint32_t a2 = packh2(sfrag[2 * kg + 1][0], sfrag[2 * kg + 1][1]);
            uint32_t a3 = packh2(sfrag[2 * kg + 1][2], sfrag[2 * kg + 1][3]);
#pragma unroll
            for (int nt = 0; nt < 8; nt++) {
                const __half* pb = &Vs[(nt * 8 + g) * 72 + kg * 16 + 2 * q];
                uint32_t b0 = *(const uint32_t*)pb;
                uint32_t b1 = *(const uint32_t*)(pb + 8);
                mma_h(o[nt], a0, a1, a2, a3, b0, b1);
            }
        }
        __syncthreads();   // protect K/V restage
    }

    // ---- normalize + write fp16 output ----
    {
        float inv0 = 1.f / l0, inv1 = 1.f / l1;
#pragma unroll
        for (int t = 0; t < 8; t++) {
            int c = hoff + t * 8 + 2 * q;
            *(uint32_t*)&O[r0q * HID + c] = packh2(o[t][0] * inv0, o[t][1] * inv0);
            *(uint32_t*)&O[r1q * HID + c] = packh2(o[t][2] * inv1, o[t][3] * inv1);
        }
    }
}

// ---------------------------------------------------------------------------
// Host launcher. Inputs: 0:X 1:position_ids 2:mask(unused) 3:Wq 4:Wk 5:Wv
//                        6:Wo 7:bo ; output f32[1,4096,1024]
// ---------------------------------------------------------------------------
extern "C" void kernel_launch(void* const* d_in, const int* in_sizes, int n_in,
                              void* d_out, int out_size) {
    const float* X  = (const float*)d_in[0];
    const int* pos  = (const int*)d_in[1];
    const float* Wq = (const float*)d_in[3];
    const float* Wk = (const float*)d_in[4];
    const float* Wv = (const float*)d_in[5];
    const float* Wo = (const float*)d_in[6];
    const float* bo = (const float*)d_in[7];
    float* out = (float*)d_out;

    __half *Xh, *Wqh, *Wkh, *Wvh, *Woh, *Qh, *Kh, *Vh, *Vth, *Ch;
    cudaGetSymbolAddress((void**)&Xh, g_Xh);
    cudaGetSymbolAddress((void**)&Wqh, g_Wqh);
    cudaGetSymbolAddress((void**)&Wkh, g_Wkh);
    cudaGetSymbolAddress((void**)&Wvh, g_Wvh);
    cudaGetSymbolAddress((void**)&Woh, g_Woh);
    cudaGetSymbolAddress((void**)&Qh, g_Qh);
    cudaGetSymbolAddress((void**)&Kh, g_Kh);
    cudaGetSymbolAddress((void**)&Vh, g_Vh);
    cudaGetSymbolAddress((void**)&Vth, g_Vth);
    cudaGetSymbolAddress((void**)&Ch, g_Ch);

    pack_all_kernel<<<8192, 256>>>(
        (const float4*)X, Xh, (const float4*)Wq, Wqh, (const float4*)Wk, Wkh,
        (const float4*)Wv, Wvh, (const float4*)Wo, Woh);

    dim3 ggrid(HID / 128, SEQ / 128);  // (8, 32)
    const int gemm_smem = 73728;

    cudaFuncSetAttribute((const void*)gemm_h<0, __half>,
                         cudaFuncAttributeMaxDynamicSharedMemorySize, gemm_smem);
    cudaFuncSetAttribute((const void*)gemm_h<1, __half>,
                         cudaFuncAttributeMaxDynamicSharedMemorySize, gemm_smem);
    cudaFuncSetAttribute((const void*)gemm_h<2, float>,
                         cudaFuncAttributeMaxDynamicSharedMemorySize, gemm_smem);

    gemm_h<1, __half><<<ggrid, 256, gemm_smem>>>(Xh, Wqh, nullptr, pos, Qh, SEQ, HID, HID);
    gemm_h<1, __half><<<ggrid, 256, gemm_smem>>>(Xh, Wkh, nullptr, pos, Kh, SEQ, HID, HID);
    gemm_h<0, __half><<<ggrid, 256, gemm_smem>>>(Xh, Wvh, nullptr, nullptr, Vh, SEQ, HID, HID);

    transpose_v<<<dim3(SEQ / 64, NH), 256>>>(Vh, Vth);

    const int flash_smem = 27648;
    cudaFuncSetAttribute((const void*)flash_h,
                         cudaFuncAttributeMaxDynamicSharedMemorySize, flash_smem);
    flash_h<<<dim3(SEQ / 64, NH), 128, flash_smem>>>(Qh, Kh, Vth, Ch);

    gemm_h<2, float><<<ggrid, 256, gemm_smem>>>(Ch, Woh, bo, nullptr, out, SEQ, HID, HID);
}

// round 11
// speedup vs baseline: 3.1986x; 1.1280x over previous
#include <cuda_runtime.h>
#include <cuda_fp16.h>
#include <math.h>
#include <stdint.h>

#define SEQ 4096
#define HID 1024
#define NH  16
#define HD  64

// Scratch (allocation-free rule: __device__ globals), all fp16
__device__ __half g_Xh[SEQ * HID];
__device__ __half g_Wqh[HID * HID];
__device__ __half g_Wkh[HID * HID];
__device__ __half g_Wvh[HID * HID];
__device__ __half g_Woh[HID * HID];
__device__ __half g_Qh[SEQ * HID];
__device__ __half g_Kh[SEQ * HID];
__device__ __half g_Vh[SEQ * HID];
__device__ __half g_Vth[SEQ * HID];   // per-head transposed V: [h][d][s]
__device__ __half g_Ch[SEQ * HID];

// ---------------------------------------------------------------------------
// helpers
// ---------------------------------------------------------------------------
__device__ __forceinline__ uint32_t sptr(const void* p) {
    return (uint32_t)__cvta_generic_to_shared(p);
}
#define CPA16(dst, src) \
    asm volatile("cp.async.cg.shared.global [%0], [%1], 16;" :: "r"(dst), "l"(src))
#define CPC() asm volatile("cp.async.commit_group;")
#define CPW(N) asm volatile("cp.async.wait_group %0;" :: "n"(N))

#define LDSM4(r0, r1, r2, r3, addr) \
    asm volatile("ldmatrix.sync.aligned.m8n8.x4.shared.b16 {%0,%1,%2,%3}, [%4];" \
                 : "=r"(r0), "=r"(r1), "=r"(r2), "=r"(r3) : "r"(addr))

__device__ __forceinline__ void mma_h(float (&d)[4], uint32_t a0, uint32_t a1,
                                      uint32_t a2, uint32_t a3,
                                      uint32_t b0, uint32_t b1) {
    asm volatile(
        "mma.sync.aligned.m16n8k16.row.col.f32.f16.f16.f32 "
        "{%0,%1,%2,%3}, {%4,%5,%6,%7}, {%8,%9}, {%0,%1,%2,%3};\n"
        : "+f"(d[0]), "+f"(d[1]), "+f"(d[2]), "+f"(d[3])
        : "r"(a0), "r"(a1), "r"(a2), "r"(a3), "r"(b0), "r"(b1));
}

__device__ __forceinline__ uint32_t packh2(float lo, float hi) {
    __half2 h = __floats2half2_rn(lo, hi);
    return *reinterpret_cast<uint32_t*>(&h);
}

// ---------------------------------------------------------------------------
// f32 -> fp16 pack, all 5 tensors in one launch.
// ---------------------------------------------------------------------------
__global__ void pack_all_kernel(const float4* __restrict__ X, __half* __restrict__ Xh,
                                const float4* __restrict__ W0, __half* __restrict__ W0h,
                                const float4* __restrict__ W1, __half* __restrict__ W1h,
                                const float4* __restrict__ W2, __half* __restrict__ W2h,
                                const float4* __restrict__ W3, __half* __restrict__ W3h) {
    int b = blockIdx.x;
    const float4* src;
    __half* dst;
    int off;
    if (b < 4096)      { src = X;  dst = Xh;  off = b * 256; }
    else if (b < 5120) { src = W0; dst = W0h; off = (b - 4096) * 256; }
    else if (b < 6144) { src = W1; dst = W1h; off = (b - 5120) * 256; }
    else if (b < 7168) { src = W2; dst = W2h; off = (b - 6144) * 256; }
    else               { src = W3; dst = W3h; off = (b - 7168) * 256; }
    int i = off + threadIdx.x;
    float4 v = src[i];
    uint2 o;
    o.x = packh2(v.x, v.y);
    o.y = packh2(v.z, v.w);
    *(uint2*)&dst[i * 4] = o;
}

// ===========================================================================
// Shared GEMM machinery: BM=BN=128, BK=64 halves, 256 thr = 8 warps (4m x 2n),
// 2-stage cp.async pipeline, ldmatrix.x4 fragment loads (pitch 72 halves).
// ===========================================================================
struct GemmCore {
    const __half* A;
    const __half* B;
    int rowBase, colBase, K;
    uint32_t sA[2], sB[2];
    int tid, lane, w, wm, wn;

    __device__ __forceinline__ void stage(int k0, int buf) {
        __half* As = (__half*)__cvta_shared_to_generic((uint64_t)sA[buf]);
        __half* Bs = (__half*)__cvta_shared_to_generic((uint64_t)sB[buf]);
#pragma unroll
        for (int t = 0; t < 8; t++) {
            int i = tid + t * 256;
            int mat = i >> 10;
            int r = (i >> 3) & 127;
            int ch = i & 7;
            const __half* src = mat ? &B[(colBase + r) * K + k0 + ch * 8]
                                    : &A[(rowBase + r) * K + k0 + ch * 8];
            uint32_t d = (mat ? sB[buf] : sA[buf]) + (r * 72 + ch * 8) * 2;
            CPA16(d, src);
        }
    }

    __device__ __forceinline__ void compute(int buf, float (*acc)[4]) {
        const uint32_t sa = sA[buf], sb = sB[buf];
        const int rA = (lane & 7) + ((lane >> 3) & 1) * 8;   // row add for A ldsm
        const int cA = (lane >> 4) * 8;                      // col add for A ldsm
        const int rB = (lane & 7) + (lane >> 4) * 8;         // row add for B ldsm
        const int cB = ((lane >> 3) & 1) * 8;                // col add for B ldsm
#pragma unroll
        for (int kg = 0; kg < 4; kg++) {
            uint32_t a[2][4];
#pragma unroll
            for (int mt = 0; mt < 2; mt++) {
                uint32_t ad = sa + ((wm * 32 + mt * 16 + rA) * 72 + kg * 16 + cA) * 2;
                LDSM4(a[mt][0], a[mt][1], a[mt][2], a[mt][3], ad);
            }
#pragma unroll
            for (int p = 0; p < 4; p++) {
                uint32_t b0, b1, b2, b3;
                uint32_t bd = sb + ((wn * 64 + p * 16 + rB) * 72 + kg * 16 + cB) * 2;
                LDSM4(b0, b1, b2, b3, bd);
                mma_h(acc[2 * p],     a[0][0], a[0][1], a[0][2], a[0][3], b0, b1);
                mma_h(acc[2 * p + 1], a[0][0], a[0][1], a[0][2], a[0][3], b2, b3);
                mma_h(acc[8 + 2 * p],     a[1][0], a[1][1], a[1][2], a[1][3], b0, b1);
                mma_h(acc[8 + 2 * p + 1], a[1][0], a[1][1], a[1][2], a[1][3], b2, b3);
            }
        }
    }
};

// ---------------------------------------------------------------------------
// Fused QKV GEMM. grid (24, 32): ct<8 -> Q (RoPE), ct<16 -> K (RoPE), else V.
// ---------------------------------------------------------------------------
__global__ __launch_bounds__(256, 2)
void qkv_gemm(const __half* __restrict__ Xh,
              const __half* __restrict__ Wq, const __half* __restrict__ Wk,
              const __half* __restrict__ Wv, const int* __restrict__ pos,
              __half* __restrict__ Qh, __half* __restrict__ Kh,
              __half* __restrict__ Vh) {
    extern __shared__ char smem[];
    const int ct = blockIdx.x;
    const int wsel = ct >> 3;
    GemmCore gc;
    gc.A = Xh;
    gc.B = (wsel == 0) ? Wq : (wsel == 1) ? Wk : Wv;
    gc.rowBase = blockIdx.y * 128;
    gc.colBase = (ct & 7) * 128;
    gc.K = HID;
    gc.sA[0] = sptr(smem);            gc.sA[1] = sptr(smem + 36864);
    gc.sB[0] = sptr(smem + 18432);    gc.sB[1] = sptr(smem + 55296);
    gc.tid = threadIdx.x;
    gc.lane = gc.tid & 31;
    gc.w = gc.tid >> 5;
    gc.wm = gc.w & 3;
    gc.wn = gc.w >> 2;
    __half* C = (wsel == 0) ? Qh : (wsel == 1) ? Kh : Vh;

    float acc[16][4];
#pragma unroll
    for (int i = 0; i < 16; i++)
#pragma unroll
        for (int j = 0; j < 4; j++) acc[i][j] = 0.f;

    gc.stage(0, 0);
    CPC();
    const int NK = HID / 64;   // 16
    for (int s = 0; s < NK; s++) {
        if (s + 1 < NK) { gc.stage((s + 1) * 64, (s + 1) & 1); CPC(); CPW(1); }
        else            { CPW(0); }
        __syncthreads();
        gc.compute(s & 1, acc);
        __syncthreads();
    }

    const int g = gc.lane >> 2, q = gc.lane & 3;
    if (wsel < 2) {   // RoPE: warp n-slab (64 cols) = one head; partners (t, t+4)
        float th[8];
#pragma unroll
        for (int t = 0; t < 4; t++)
#pragma unroll
            for (int b = 0; b < 2; b++) {
                int j = t * 8 + 2 * q + b;
                th[t * 2 + b] = expf(-(float)j * (9.210340371976184f / 32.0f));
            }
#pragma unroll
        for (int mt = 0; mt < 2; mt++) {
            int r0 = gc.rowBase + gc.wm * 32 + mt * 16 + g;
            float p0 = (float)pos[r0];
            float p1 = (float)pos[r0 + 8];
#pragma unroll
            for (int t = 0; t < 4; t++) {
#pragma unroll
                for (int jj = 0; jj < 4; jj++) {
                    float pv = (jj < 2) ? p0 : p1;
                    float sn, cs;
                    sincosf(pv * th[t * 2 + (jj & 1)], &sn, &cs);
                    float x1 = acc[mt * 8 + t][jj];
                    float x2 = acc[mt * 8 + t + 4][jj];
                    acc[mt * 8 + t][jj]     = x1 * cs - x2 * sn;
                    acc[mt * 8 + t + 4][jj] = x1 * sn + x2 * cs;
                }
            }
        }
    }

#pragma unroll
    for (int mt = 0; mt < 2; mt++) {
#pragma unroll
        for (int t = 0; t < 8; t++) {
            int r0 = gc.rowBase + gc.wm * 32 + mt * 16 + g;
            int c0 = gc.colBase + gc.wn * 64 + t * 8 + 2 * q;
            float* d = acc[mt * 8 + t];
            *(uint32_t*)&C[r0 * HID + c0] = packh2(d[0], d[1]);
            *(uint32_t*)&C[(r0 + 8) * HID + c0] = packh2(d[2], d[3]);
        }
    }
}

// ---------------------------------------------------------------------------
// Output GEMM: out = C @ Wo^T + bo (f32 output).
// ---------------------------------------------------------------------------
__global__ __launch_bounds__(256, 2)
void out_gemm(const __half* __restrict__ Ch, const __half* __restrict__ Wo,
              const float* __restrict__ bias, float* __restrict__ C) {
    extern __shared__ char smem[];
    GemmCore gc;
    gc.A = Ch;
    gc.B = Wo;
    gc.rowBase = blockIdx.y * 128;
    gc.colBase = blockIdx.x * 128;
    gc.K = HID;
    gc.sA[0] = sptr(smem);            gc.sA[1] = sptr(smem + 36864);
    gc.sB[0] = sptr(smem + 18432);    gc.sB[1] = sptr(smem + 55296);
    gc.tid = threadIdx.x;
    gc.lane = gc.tid & 31;
    gc.w = gc.tid >> 5;
    gc.wm = gc.w & 3;
    gc.wn = gc.w >> 2;

    float acc[16][4];
#pragma unroll
    for (int i = 0; i < 16; i++)
#pragma unroll
        for (int j = 0; j < 4; j++) acc[i][j] = 0.f;

    gc.stage(0, 0);
    CPC();
    const int NK = HID / 64;
    for (int s = 0; s < NK; s++) {
        if (s + 1 < NK) { gc.stage((s + 1) * 64, (s + 1) & 1); CPC(); CPW(1); }
        else            { CPW(0); }
        __syncthreads();
        gc.compute(s & 1, acc);
        __syncthreads();
    }

    const int g = gc.lane >> 2, q = gc.lane & 3;
#pragma unroll
    for (int mt = 0; mt < 2; mt++) {
#pragma unroll
        for (int t = 0; t < 8; t++) {
            int r0 = gc.rowBase + gc.wm * 32 + mt * 16 + g;
            int c0 = gc.colBase + gc.wn * 64 + t * 8 + 2 * q;
            float bb0 = bias[c0], bb1 = bias[c0 + 1];
            float* d = acc[mt * 8 + t];
            *(float2*)&C[r0 * HID + c0] = make_float2(d[0] + bb0, d[1] + bb1);
            *(float2*)&C[(r0 + 8) * HID + c0] = make_float2(d[2] + bb0, d[3] + bb1);
        }
    }
}

// ---------------------------------------------------------------------------
// Per-head V transpose: Vt[h][d][s] = V[s][h*64+d].
// ---------------------------------------------------------------------------
__global__ void transpose_v(const __half* __restrict__ V, __half* __restrict__ Vt) {
    __shared__ __half ts[64][72];
    const int tid = threadIdx.x;
    const int s0 = blockIdx.x * 64;
    const int h = blockIdx.y;
#pragma unroll
    for (int t = 0; t < 8; t++) {
        int i = tid + t * 256;
        int r = i >> 5, c2 = (i & 31) * 2;
        *(uint32_t*)&ts[r][c2] = *(const uint32_t*)&V[(s0 + r) * HID + h * 64 + c2];
    }
    __syncthreads();
#pragma unroll
    for (int t = 0; t < 8; t++) {
        int i = tid + t * 256;
        int d = i >> 5, s2 = (i & 31) * 2;
        __half2 v = __halves2half2(ts[s2][d], ts[s2 + 1][d]);
        *(uint32_t*)&Vt[(h * 64 + d) * SEQ + s0 + s2] = *reinterpret_cast<uint32_t*>(&v);
    }
}

// ---------------------------------------------------------------------------
// Causal flash attention, fp16 MMA, f32 softmax/accum, ldmatrix frag loads.
// BR=64, BC=64, 128 threads. P in registers; m/l in registers (quad shfl).
// smem 27,648 B -> 4 CTAs/SM.
// ---------------------------------------------------------------------------
__global__ __launch_bounds__(128, 4)
void flash_h(const __half* __restrict__ Q, const __half* __restrict__ K,
             const __half* __restrict__ Vt, __half* __restrict__ O) {
    extern __shared__ char smem[];
    __half* Qs = (__half*)smem;              // 64 x 72
    __half* Ks = (__half*)(smem + 9216);     // 64 x 72
    __half* Vs = (__half*)(smem + 18432);    // 64 x 72 (d-major, s contiguous)
    const uint32_t sQ = sptr(Qs), sK = sptr(Ks), sV = sptr(Vs);

    const int tid = threadIdx.x;
    const int lane = tid & 31;
    const int w = tid >> 5;
    const int g = lane >> 2;
    const int q = lane & 3;
    const int qb = gridDim.x - 1 - blockIdx.x;
    const int h = blockIdx.y;
    const int qBase = qb * 64;
    const int hoff = h * HD;
    const float scale = 0.125f;

    const int rA = (lane & 7) + ((lane >> 3) & 1) * 8;
    const int cA = (lane >> 4) * 8;
    const int rB = (lane & 7) + (lane >> 4) * 8;
    const int cB = ((lane >> 3) & 1) * 8;

#pragma unroll
    for (int t = 0; t < 4; t++) {
        int i = tid + t * 128;
        int r = i >> 3, ch = i & 7;
        CPA16(sQ + (r * 72 + ch * 8) * 2, &Q[(qBase + r) * HID + hoff + ch * 8]);
    }

    float o[8][4];
#pragma unroll
    for (int t = 0; t < 8; t++)
#pragma unroll
        for (int j = 0; j < 4; j++) o[t][j] = 0.f;
    float m0 = -1e30f, m1 = -1e30f, l0 = 0.f, l1 = 0.f;

    const int r0q = qBase + w * 16 + g;
    const int r1q = r0q + 8;

    const int nkb = qb + 1;
    for (int kb = 0; kb < nkb; kb++) {
        const int kBase = kb * 64;
#pragma unroll
        for (int t = 0; t < 8; t++) {
            int i = tid + t * 128;
            int mat = i >> 9;
            int r = (i >> 3) & 63, ch = i & 7;
            if (mat == 0)
                CPA16(sK + (r * 72 + ch * 8) * 2, &K[(kBase + r) * HID + hoff + ch * 8]);
            else
                CPA16(sV + (r * 72 + ch * 8) * 2, &Vt[(h * 64 + r) * SEQ + kBase + ch * 8]);
        }
        CPC(); CPW(0);
        __syncthreads();

        // ---- S = Q K^T ----
        float sfrag[8][4];
#pragma unroll
        for (int t = 0; t < 8; t++)
#pragma unroll
            for (int j = 0; j < 4; j++) sfrag[t][j] = 0.f;

#pragma unroll
        for (int kg = 0; kg < 4; kg++) {
            uint32_t a0, a1, a2, a3;
            LDSM4(a0, a1, a2, a3, sQ + ((w * 16 + rA) * 72 + kg * 16 + cA) * 2);
#pragma unroll
            for (int p = 0; p < 4; p++) {
                uint32_t b0, b1, b2, b3;
                LDSM4(b0, b1, b2, b3, sK + ((p * 16 + rB) * 72 + kg * 16 + cB) * 2);
                mma_h(sfrag[2 * p],     a0, a1, a2, a3, b0, b1);
                mma_h(sfrag[2 * p + 1], a0, a1, a2, a3, b2, b3);
            }
        }

        // ---- scale (+ causal mask on diagonal tile) ----
#pragma unroll
        for (int nt = 0; nt < 8; nt++)
#pragma unroll
            for (int j = 0; j < 4; j++) sfrag[nt][j] *= scale;
        if (kb == qb) {
#pragma unroll
            for (int nt = 0; nt < 8; nt++) {
                int c = kBase + nt * 8 + 2 * q;
                if (c     > r0q) sfrag[nt][0] = -1e30f;
                if (c + 1 > r0q) sfrag[nt][1] = -1e30f;
                if (c     > r1q) sfrag[nt][2] = -1e30f;
                if (c + 1 > r1q) sfrag[nt][3] = -1e30f;
            }
        }

        // ---- online softmax in registers ----
        float mx0 = -1e30f, mx1 = -1e30f;
#pragma unroll
        for (int nt = 0; nt < 8; nt++) {
            mx0 = fmaxf(mx0, fmaxf(sfrag[nt][0], sfrag[nt][1]));
            mx1 = fmaxf(mx1, fmaxf(sfrag[nt][2], sfrag[nt][3]));
        }
        mx0 = fmaxf(mx0, __shfl_xor_sync(0xffffffffu, mx0, 1));
        mx0 = fmaxf(mx0, __shfl_xor_sync(0xffffffffu, mx0, 2));
        mx1 = fmaxf(mx1, __shfl_xor_sync(0xffffffffu, mx1, 1));
        mx1 = fmaxf(mx1, __shfl_xor_sync(0xffffffffu, mx1, 2));

        float mn0 = fmaxf(m0, mx0), mn1 = fmaxf(m1, mx1);
        float al0 = __expf(m0 - mn0), al1 = __expf(m1 - mn1);
        m0 = mn0; m1 = mn1;

        float s0 = 0.f, s1 = 0.f;
#pragma unroll
        for (int nt = 0; nt < 8; nt++) {
            sfrag[nt][0] = __expf(sfrag[nt][0] - m0);
            sfrag[nt][1] = __expf(sfrag[nt][1] - m0);
            sfrag[nt][2] = __expf(sfrag[nt][2] - m1);
            sfrag[nt][3] = __expf(sfrag[nt][3] - m1);
            s0 += sfrag[nt][0] + sfrag[nt][1];
            s1 += sfrag[nt][2] + sfrag[nt][3];
        }
        s0 += __shfl_xor_sync(0xffffffffu, s0, 1);
        s0 += __shfl_xor_sync(0xffffffffu, s0, 2);
        s1 += __shfl_xor_sync(0xffffffffu, s1, 1);
        s1 += __shfl_xor_sync(0xffffffffu, s1, 2);
        l0 = l0 * al0 + s0;
        l1 = l1 * al1 + s1;

#pragma unroll
        for (int t = 0; t < 8; t++) {
            o[t][0] *= al0; o[t][1] *= al0;
            o[t][2] *= al1; o[t][3] *= al1;
        }

        // ---- O += P V (P C-frag packs into A-frag) ----
#pragma unroll
        for (int kg = 0; kg < 4; kg++) {
            uint32_t a0 = packh2(sfrag[2 * kg][0], sfrag[2 * kg][1]);
            uint32_t a1 = packh2(sfrag[2 * kg][2], sfrag[2 * kg][3]);
            uint32_t a2 = packh2(sfrag[2 * kg + 1][0], sfrag[2 * kg + 1][1]);
            uint32_t a3 = packh2(sfrag[2 * kg + 1][2], sfrag[2 * kg + 1][3]);
#pragma unroll
            for (int p = 0; p < 4; p++) {
                uint32_t b0, b1, b2, b3;
                LDSM4(b0, b1, b2, b3, sV + ((p * 16 + rB) * 72 + kg * 16 + cB) * 2);
                mma_h(o[2 * p],     a0, a1, a2, a3, b0, b1);
                mma_h(o[2 * p + 1], a0, a1, a2, a3, b2, b3);
            }
        }
        __syncthreads();
    }

    // ---- normalize + write fp16 output ----
    {
        float inv0 = 1.f / l0, inv1 = 1.f / l1;
#pragma unroll
        for (int t = 0; t < 8; t++) {
            int c = hoff + t * 8 + 2 * q;
            *(uint32_t*)&O[r0q * HID + c] = packh2(o[t][0] * inv0, o[t][1] * inv0);
            *(uint32_t*)&O[r1q * HID + c] = packh2(o[t][2] * inv1, o[t][3] * inv1);
        }
    }
}

// ---------------------------------------------------------------------------
// Host launcher. Inputs: 0:X 1:position_ids 2:mask(unused) 3:Wq 4:Wk 5:Wv
//                        6:Wo 7:bo ; output f32[1,4096,1024]
// ---------------------------------------------------------------------------
extern "C" void kernel_launch(void* const* d_in, const int* in_sizes, int n_in,
                              void* d_out, int out_size) {
    const float* X  = (const float*)d_in[0];
    const int* pos  = (const int*)d_in[1];
    const float* Wq = (const float*)d_in[3];
    const float* Wk = (const float*)d_in[4];
    const float* Wv = (const float*)d_in[5];
    const float* Wo = (const float*)d_in[6];
    const float* bo = (const float*)d_in[7];
    float* out = (float*)d_out;

    __half *Xh, *Wqh, *Wkh, *Wvh, *Woh, *Qh, *Kh, *Vh, *Vth, *Ch;
    cudaGetSymbolAddress((void**)&Xh, g_Xh);
    cudaGetSymbolAddress((void**)&Wqh, g_Wqh);
    cudaGetSymbolAddress((void**)&Wkh, g_Wkh);
    cudaGetSymbolAddress((void**)&Wvh, g_Wvh);
    cudaGetSymbolAddress((void**)&Woh, g_Woh);
    cudaGetSymbolAddress((void**)&Qh, g_Qh);
    cudaGetSymbolAddress((void**)&Kh, g_Kh);
    cudaGetSymbolAddress((void**)&Vh, g_Vh);
    cudaGetSymbolAddress((void**)&Vth, g_Vth);
    cudaGetSymbolAddress((void**)&Ch, g_Ch);

    pack_all_kernel<<<8192, 256>>>(
        (const float4*)X, Xh, (const float4*)Wq, Wqh, (const float4*)Wk, Wkh,
        (const float4*)Wv, Wvh, (const float4*)Wo, Woh);

    const int gemm_smem = 73728;
    cudaFuncSetAttribute((const void*)qkv_gemm,
                         cudaFuncAttributeMaxDynamicSharedMemorySize, gemm_smem);
    cudaFuncSetAttribute((const void*)out_gemm,
                         cudaFuncAttributeMaxDynamicSharedMemorySize, gemm_smem);

    qkv_gemm<<<dim3(24, SEQ / 128), 256, gemm_smem>>>(Xh, Wqh, Wkh, Wvh, pos,
                                                      Qh, Kh, Vh);

    transpose_v<<<dim3(SEQ / 64, NH), 256>>>(Vh, Vth);

    const int flash_smem = 27648;
    cudaFuncSetAttribute((const void*)flash_h,
                         cudaFuncAttributeMaxDynamicSharedMemorySize, flash_smem);
    flash_h<<<dim3(SEQ / 64, NH), 128, flash_smem>>>(Qh, Kh, Vth, Ch);

    out_gemm<<<dim3(HID / 128, SEQ / 128), 256, gemm_smem>>>(Ch, Woh, bo, out);
}